// round 6
// baseline (speedup 1.0000x reference)
#include <cuda_runtime.h>
#include <cuda_fp16.h>
#include <math.h>
#include <stdint.h>

// Problem constants
constexpr int BATCH   = 32;
constexpr int HDIM    = 56;
constexpr int C_DIM   = 384;
constexpr int NHEADS  = 12;
constexpr int HEADD   = 32;
constexpr int WS      = 7;
constexpr int SHIFT   = 3;
constexpr int NWIN    = 49;
constexpr int M_TOK   = BATCH * HDIM * HDIM;   // 100352
constexpr int MLP_HID = 4 * C_DIM;             // 1536

constexpr int NSTAGE     = 3;
constexpr int STAGE_B    = 32768;              // A 16KB + B 16KB (fp16, k64)
constexpr int SMEM_BYTES = NSTAGE * STAGE_B;   // 96KB per CTA

// Scratch buffers (device globals: no allocation allowed)
__device__ __align__(256) __half g_ln [(size_t)M_TOK * C_DIM];
__device__ __align__(256) __half g_qkv[(size_t)M_TOK * 3 * C_DIM];
__device__ __align__(256) __half g_o  [(size_t)M_TOK * C_DIM];
__device__ __align__(256) float  g_h  [(size_t)M_TOK * C_DIM];
__device__ __align__(256) __half g_a1 [(size_t)M_TOK * MLP_HID];
// fp16 transposed weights [N][K]
__device__ __align__(256) __half g_bt_qkv [(size_t)3 * C_DIM * C_DIM];
__device__ __align__(256) __half g_bt_proj[(size_t)C_DIM * C_DIM];
__device__ __align__(256) __half g_bt_fc1 [(size_t)MLP_HID * C_DIM];
__device__ __align__(256) __half g_bt_fc2 [(size_t)C_DIM * MLP_HID];

// ---------------------------------------------------------------------------
// asm helpers (base-arch only: cp.async sm80, ldmatrix sm75, mma.sync sm80)
// ---------------------------------------------------------------------------
__device__ __forceinline__ uint32_t smem_u32(const void* p) {
    uint32_t a;
    asm("{ .reg .u64 t; cvta.to.shared.u64 t, %1; cvt.u32.u64 %0, t; }"
        : "=r"(a) : "l"(p));
    return a;
}
__device__ __forceinline__ void cp16(uint32_t dst, const void* src) {
    asm volatile("cp.async.cg.shared.global [%0], [%1], 16;"
                 :: "r"(dst), "l"(src) : "memory");
}
__device__ __forceinline__ void cp_commit() {
    asm volatile("cp.async.commit_group;" ::: "memory");
}
template <int N>
__device__ __forceinline__ void cp_wait() {
    asm volatile("cp.async.wait_group %0;" :: "n"(N) : "memory");
}
__device__ __forceinline__ void ldmx4(uint32_t& r0, uint32_t& r1,
                                      uint32_t& r2, uint32_t& r3, uint32_t addr) {
    asm volatile("ldmatrix.sync.aligned.m8n8.x4.shared.b16 {%0,%1,%2,%3}, [%4];"
                 : "=r"(r0), "=r"(r1), "=r"(r2), "=r"(r3) : "r"(addr));
}
// fp16-accumulate MMA: c regs are packed half2
__device__ __forceinline__ void mma16816h(uint32_t* c, const uint32_t* a,
                                          const uint32_t* b) {
    asm volatile(
        "mma.sync.aligned.m16n8k16.row.col.f16.f16.f16.f16 "
        "{%0,%1}, {%2,%3,%4,%5}, {%6,%7}, {%0,%1};"
        : "+r"(c[0]), "+r"(c[1])
        : "r"(a[0]), "r"(a[1]), "r"(a[2]), "r"(a[3]), "r"(b[0]), "r"(b[1]));
}
// smem tile: [128 rows][64 fp16] = 128B rows (8x16B chunks), XOR-8 swizzle
__device__ __forceinline__ uint32_t sa_off(int row, int c4) {
    return (uint32_t)(row * 128 + ((c4 ^ (row & 7)) << 4));
}
__device__ __forceinline__ float gelu(float v) {
    return 0.5f * v * (1.0f + erff(v * 0.70710678118654752f));
}

// ---------------------------------------------------------------------------
// Weight prep: W[K][N] fp32 -> Wt[N][K] fp16
// ---------------------------------------------------------------------------
__global__ __launch_bounds__(256) void prep_w(const float* __restrict__ W,
                                              __half* __restrict__ Wt,
                                              int K, int N) {
    int idx = blockIdx.x * 256 + threadIdx.x;
    if (idx >= K * N) return;
    int k = idx / N, n = idx - k * N;
    Wt[(size_t)n * K + k] = __float2half_rn(W[idx]);
}

// ---------------------------------------------------------------------------
// fp16 HMMA GEMM, dual accumulator: fp16 acc within a k64 chunk, promoted to
// fp32 once per chunk (error bounded to <=64 fp16 adds).
// 128x128 CTA tile, 128 thr, 4 warps (2x2 -> 64x64 warp tile), 3-stage cp.async.
// EPI: 0 = +bias -> half ; 1 = +bias+res -> float ; 2 = gelu(+bias) -> half
// ---------------------------------------------------------------------------
template <int EPI>
__global__ __launch_bounds__(128, 2)
void gemm_hmma(const __half* __restrict__ A, const __half* __restrict__ Bt,
               const float* __restrict__ bias, const float* __restrict__ R,
               void* __restrict__ out, int M, int N, int K) {
    extern __shared__ __align__(128) char smem[];
    uint32_t sbase = smem_u32(smem);

    int tid = threadIdx.x, warp = tid >> 5, lane = tid & 31;
    int wm = warp >> 1, wn = warp & 1;
    int m0 = blockIdx.y * 128, n0 = blockIdx.x * 128;
    int NC = K >> 6;   // k64 chunks

    float facc[4][8][4];
    #pragma unroll
    for (int i = 0; i < 4; i++)
        #pragma unroll
        for (int j = 0; j < 8; j++)
            #pragma unroll
            for (int e = 0; e < 4; e++) facc[i][j][e] = 0.0f;

    auto load_chunk = [&](int kc, int s) {
        uint32_t ast = sbase + s * STAGE_B;
        uint32_t bst = ast + 16384;
        #pragma unroll
        for (int t = 0; t < 8; t++) {
            int seg = tid + t * 128;
            int row = seg >> 3, q = seg & 7;
            cp16(ast + sa_off(row, q),
                 A + (size_t)(m0 + row) * K + kc * 64 + q * 8);
            cp16(bst + sa_off(row, q),
                 Bt + (size_t)(n0 + row) * K + kc * 64 + q * 8);
        }
    };

    #pragma unroll
    for (int c = 0; c < NSTAGE - 1; c++) { load_chunk(c, c); cp_commit(); }

    int s_cur = 0, s_nxt = NSTAGE - 1;
    for (int c = 0; c < NC; c++) {
        cp_wait<NSTAGE - 2>();
        __syncthreads();
        int cn = c + NSTAGE - 1;
        if (cn < NC) load_chunk(cn, s_nxt);
        cp_commit();
        if (++s_nxt == NSTAGE) s_nxt = 0;

        uint32_t ast = sbase + s_cur * STAGE_B;
        uint32_t bst = ast + 16384;
        if (++s_cur == NSTAGE) s_cur = 0;

        // fp16 chunk accumulators (zeroed each chunk)
        uint32_t hacc[4][8][2];
        #pragma unroll
        for (int i = 0; i < 4; i++)
            #pragma unroll
            for (int j = 0; j < 8; j++)
                hacc[i][j][0] = hacc[i][j][1] = 0u;

        #pragma unroll
        for (int kk = 0; kk < 4; kk++) {
            uint32_t a[4][4], b[4][4];
            #pragma unroll
            for (int i = 0; i < 4; i++) {
                int row = wm * 64 + i * 16 + (lane & 15);
                int c4  = kk * 2 + (lane >> 4);
                ldmx4(a[i][0], a[i][1], a[i][2], a[i][3], ast + sa_off(row, c4));
            }
            #pragma unroll
            for (int jp = 0; jp < 4; jp++) {
                int row = wn * 64 + jp * 16 + (lane & 7) + ((lane >> 4) << 3);
                int c4  = kk * 2 + ((lane >> 3) & 1);
                ldmx4(b[jp][0], b[jp][1], b[jp][2], b[jp][3], bst + sa_off(row, c4));
            }
            #pragma unroll
            for (int i = 0; i < 4; i++)
                #pragma unroll
                for (int jp = 0; jp < 4; jp++) {
                    mma16816h(hacc[i][jp * 2 + 0], a[i], &b[jp][0]);
                    mma16816h(hacc[i][jp * 2 + 1], a[i], &b[jp][2]);
                }
        }

        // promote chunk partials to fp32 (FMA pipe, overlaps next chunk's loads)
        #pragma unroll
        for (int i = 0; i < 4; i++)
            #pragma unroll
            for (int j = 0; j < 8; j++) {
                float2 f0 = __half22float2(
                    *reinterpret_cast<__half2*>(&hacc[i][j][0]));
                float2 f1 = __half22float2(
                    *reinterpret_cast<__half2*>(&hacc[i][j][1]));
                facc[i][j][0] += f0.x; facc[i][j][1] += f0.y;
                facc[i][j][2] += f1.x; facc[i][j][3] += f1.y;
            }
    }

    // register epilogue
    int rbase = m0 + wm * 64 + (lane >> 2);
    #pragma unroll
    for (int i = 0; i < 4; i++) {
        #pragma unroll
        for (int j = 0; j < 8; j++) {
            int col = n0 + wn * 64 + j * 8 + ((lane & 3) << 1);
            float b0 = bias[col], b1 = bias[col + 1];
            #pragma unroll
            for (int hm = 0; hm < 2; hm++) {
                int row = rbase + i * 16 + hm * 8;
                float v0 = facc[i][j][hm * 2 + 0] + b0;
                float v1 = facc[i][j][hm * 2 + 1] + b1;
                if (EPI == 1) {
                    const float2 r2 = *reinterpret_cast<const float2*>(
                        R + (size_t)row * N + col);
                    v0 += r2.x; v1 += r2.y;
                    *reinterpret_cast<float2*>((float*)out + (size_t)row * N + col)
                        = make_float2(v0, v1);
                } else {
                    if (EPI == 2) { v0 = gelu(v0); v1 = gelu(v1); }
                    *reinterpret_cast<__half2*>((__half*)out + (size_t)row * N + col)
                        = __floats2half2_rn(v0, v1);
                }
            }
        }
    }
}

// ---------------------------------------------------------------------------
// LayerNorm: one warp per token, fp32 in -> fp16 out
// ---------------------------------------------------------------------------
__global__ __launch_bounds__(256) void ln_kernel(const float* __restrict__ x,
                                                 const float* __restrict__ g,
                                                 const float* __restrict__ b,
                                                 __half* __restrict__ y) {
    int warp = threadIdx.x >> 5, lane = threadIdx.x & 31;
    int m = blockIdx.x * 8 + warp;
    const float4* xr = reinterpret_cast<const float4*>(x + (size_t)m * C_DIM);
    float4 v0 = xr[lane], v1 = xr[lane + 32], v2 = xr[lane + 64];

    float s  = v0.x + v0.y + v0.z + v0.w + v1.x + v1.y + v1.z + v1.w
             + v2.x + v2.y + v2.z + v2.w;
    float sq = v0.x*v0.x + v0.y*v0.y + v0.z*v0.z + v0.w*v0.w
             + v1.x*v1.x + v1.y*v1.y + v1.z*v1.z + v1.w*v1.w
             + v2.x*v2.x + v2.y*v2.y + v2.z*v2.z + v2.w*v2.w;
    #pragma unroll
    for (int o = 16; o; o >>= 1) {
        s  += __shfl_xor_sync(0xffffffffu, s,  o);
        sq += __shfl_xor_sync(0xffffffffu, sq, o);
    }
    float mean = s * (1.0f / 384.0f);
    float var  = sq * (1.0f / 384.0f) - mean * mean;
    float rstd = rsqrtf(var + 1e-5f);

    const float4* gr = reinterpret_cast<const float4*>(g);
    const float4* br = reinterpret_cast<const float4*>(b);
    __half2* yr = reinterpret_cast<__half2*>(y + (size_t)m * C_DIM);
    #pragma unroll
    for (int t = 0; t < 3; t++) {
        int p = lane + 32 * t;
        float4 xv = (t == 0) ? v0 : (t == 1) ? v1 : v2;
        float4 gv = gr[p], bv = br[p];
        yr[p * 2 + 0] = __floats2half2_rn((xv.x - mean) * rstd * gv.x + bv.x,
                                          (xv.y - mean) * rstd * gv.y + bv.y);
        yr[p * 2 + 1] = __floats2half2_rn((xv.z - mean) * rstd * gv.z + bv.z,
                                          (xv.w - mean) * rstd * gv.w + bv.w);
    }
}

// ---------------------------------------------------------------------------
// Windowed shifted attention: one block per (head, window); fp16 I/O;
// float4-vectorized QK and PV loops.
// ---------------------------------------------------------------------------
__global__ __launch_bounds__(256) void attn_kernel(const __half* __restrict__ qkv,
                                                   const float* __restrict__ table,
                                                   const int* __restrict__ relidx,
                                                   __half* __restrict__ o) {
    __shared__ __align__(16) float qs[NWIN][36], ks[NWIN][36], vs[NWIN][36];
    __shared__ float ss[NWIN][52];
    __shared__ int   sidx[NWIN];

    int head = blockIdx.x;
    int w    = blockIdx.y;
    int tid  = threadIdx.x, warp = tid >> 5, lane = tid & 31;

    int b  = w >> 6;
    int wr = w & 63;
    int wi = wr >> 3, wj = wr & 7;

    if (tid < NWIN) {
        int i = tid / 7, j = tid - 7 * (tid / 7);
        int rr = wi * 7 + i + SHIFT; if (rr >= HDIM) rr -= HDIM;
        int cc = wj * 7 + j + SHIFT; if (cc >= HDIM) cc -= HDIM;
        sidx[tid] = b * (HDIM * HDIM) + rr * HDIM + cc;
    }
    __syncthreads();

    for (int r = warp; r < NWIN; r += 8) {
        const __half* base = qkv + (size_t)sidx[r] * (3 * C_DIM) + head * HEADD;
        qs[r][lane] = __half2float(base[lane]);
        ks[r][lane] = __half2float(base[C_DIM + lane]);
        vs[r][lane] = __half2float(base[2 * C_DIM + lane]);
    }
    __syncthreads();

    const float scale = 0.17677669529663687f;
    for (int e = tid; e < NWIN * NWIN; e += 256) {
        int i = e / NWIN, j = e - i * NWIN;
        const float4* q4 = reinterpret_cast<const float4*>(&qs[i][0]);
        const float4* k4 = reinterpret_cast<const float4*>(&ks[j][0]);
        float sx = 0.f, sy = 0.f, sz = 0.f, sw = 0.f;
        #pragma unroll
        for (int t = 0; t < 8; t++) {
            float4 a = q4[t], c = k4[t];
            sx += a.x * c.x; sy += a.y * c.y; sz += a.z * c.z; sw += a.w * c.w;
        }
        ss[i][j] = (sx + sy + sz + sw) * scale + table[relidx[e] * NHEADS + head];
    }
    __syncthreads();

    for (int i = warp; i < NWIN; i += 8) {
        float mx = -1e30f;
        for (int j = lane; j < NWIN; j += 32) mx = fmaxf(mx, ss[i][j]);
        #pragma unroll
        for (int off = 16; off; off >>= 1)
            mx = fmaxf(mx, __shfl_xor_sync(0xffffffffu, mx, off));
        float sum = 0.0f;
        for (int j = lane; j < NWIN; j += 32) {
            float p = __expf(ss[i][j] - mx);
            ss[i][j] = p;
            sum += p;
        }
        #pragma unroll
        for (int off = 16; off; off >>= 1)
            sum += __shfl_xor_sync(0xffffffffu, sum, off);
        float inv = 1.0f / sum;
        for (int j = lane; j < NWIN; j += 32) ss[i][j] *= inv;
    }
    __syncthreads();

    for (int e = tid; e < NWIN * 8; e += 256) {
        int i = e >> 3, dq = e & 7;
        float ax = 0.f, ay = 0.f, az = 0.f, aw = 0.f;
        #pragma unroll 7
        for (int j = 0; j < NWIN; j++) {
            float p = ss[i][j];
            float4 v = *reinterpret_cast<const float4*>(&vs[j][dq * 4]);
            ax += p * v.x; ay += p * v.y; az += p * v.z; aw += p * v.w;
        }
        __half2 h0 = __floats2half2_rn(ax, ay);
        __half2 h1 = __floats2half2_rn(az, aw);
        uint2 pk = make_uint2(*reinterpret_cast<uint32_t*>(&h0),
                              *reinterpret_cast<uint32_t*>(&h1));
        *reinterpret_cast<uint2*>(o + (size_t)sidx[i] * C_DIM + head * HEADD + dq * 4)
            = pk;
    }
}

// ---------------------------------------------------------------------------
extern "C" void kernel_launch(void* const* d_in, const int* in_sizes, int n_in,
                              void* d_out, int out_size) {
    const float* x      = (const float*)d_in[0];
    const float* n1g    = (const float*)d_in[1];
    const float* n1b    = (const float*)d_in[2];
    const float* qkvw   = (const float*)d_in[3];
    const float* qkvb   = (const float*)d_in[4];
    const float* projw  = (const float*)d_in[5];
    const float* projb  = (const float*)d_in[6];
    const float* table  = (const float*)d_in[7];
    const float* n2g    = (const float*)d_in[8];
    const float* n2b    = (const float*)d_in[9];
    const float* fc1w   = (const float*)d_in[10];
    const float* fc1b   = (const float*)d_in[11];
    const float* fc2w   = (const float*)d_in[12];
    const float* fc2b   = (const float*)d_in[13];
    const int*   relidx = (const int*)d_in[14];
    float* out = (float*)d_out;

    __half *ln, *qkv, *o, *a1, *btq, *btp, *bt1, *bt2;
    float *h;
    cudaGetSymbolAddress((void**)&ln,  g_ln);
    cudaGetSymbolAddress((void**)&qkv, g_qkv);
    cudaGetSymbolAddress((void**)&o,   g_o);
    cudaGetSymbolAddress((void**)&h,   g_h);
    cudaGetSymbolAddress((void**)&a1,  g_a1);
    cudaGetSymbolAddress((void**)&btq, g_bt_qkv);
    cudaGetSymbolAddress((void**)&btp, g_bt_proj);
    cudaGetSymbolAddress((void**)&bt1, g_bt_fc1);
    cudaGetSymbolAddress((void**)&bt2, g_bt_fc2);

    cudaFuncSetAttribute(gemm_hmma<0>, cudaFuncAttributeMaxDynamicSharedMemorySize, SMEM_BYTES);
    cudaFuncSetAttribute(gemm_hmma<1>, cudaFuncAttributeMaxDynamicSharedMemorySize, SMEM_BYTES);
    cudaFuncSetAttribute(gemm_hmma<2>, cudaFuncAttributeMaxDynamicSharedMemorySize, SMEM_BYTES);

    // weight prep (fp32 [K][N] -> fp16 [N][K])
    prep_w<<<(C_DIM * 3 * C_DIM) / 256, 256>>>(qkvw, btq, C_DIM, 3 * C_DIM);
    prep_w<<<(C_DIM * C_DIM) / 256,     256>>>(projw, btp, C_DIM, C_DIM);
    prep_w<<<(C_DIM * MLP_HID) / 256,   256>>>(fc1w, bt1, C_DIM, MLP_HID);
    prep_w<<<(MLP_HID * C_DIM) / 256,   256>>>(fc2w, bt2, MLP_HID, C_DIM);

    // 1) LN1: x -> ln (fp16)
    ln_kernel<<<M_TOK / 8, 256>>>(x, n1g, n1b, ln);
    // 2) qkv = ln @ qkv_w + b   (fp16 out)
    gemm_hmma<0><<<dim3(3 * C_DIM / 128, M_TOK / 128), 128, SMEM_BYTES>>>(
        ln, btq, qkvb, nullptr, qkv, M_TOK, 3 * C_DIM, C_DIM);
    // 3) windowed attention (shift folded into indices), fp16 out
    attn_kernel<<<dim3(NHEADS, 2048), 256>>>(qkv, table, relidx, o);
    // 4) h = x + proj(o)   (fp32 out)
    gemm_hmma<1><<<dim3(C_DIM / 128, M_TOK / 128), 128, SMEM_BYTES>>>(
        o, btp, projb, x, h, M_TOK, C_DIM, C_DIM);
    // 5) LN2: h -> ln (fp16)
    ln_kernel<<<M_TOK / 8, 256>>>(h, n2g, n2b, ln);
    // 6) a1 = gelu(fc1(ln))  (fp16 out)
    gemm_hmma<2><<<dim3(MLP_HID / 128, M_TOK / 128), 128, SMEM_BYTES>>>(
        ln, bt1, fc1b, nullptr, a1, M_TOK, MLP_HID, C_DIM);
    // 7) out = h + fc2(a1)   (fp32 out)
    gemm_hmma<1><<<dim3(C_DIM / 128, M_TOK / 128), 128, SMEM_BYTES>>>(
        a1, bt2, fc2b, h, out, M_TOK, C_DIM, MLP_HID);
}

// round 7
// speedup vs baseline: 1.1716x; 1.1716x over previous
#include <cuda_runtime.h>
#include <cuda_fp16.h>
#include <math.h>
#include <stdint.h>

// Problem constants
constexpr int BATCH   = 32;
constexpr int HDIM    = 56;
constexpr int C_DIM   = 384;
constexpr int NHEADS  = 12;
constexpr int HEADD   = 32;
constexpr int WS      = 7;
constexpr int SHIFT   = 3;
constexpr int NWIN    = 49;
constexpr int M_TOK   = BATCH * HDIM * HDIM;   // 100352
constexpr int MLP_HID = 4 * C_DIM;             // 1536

constexpr int NSTAGE     = 3;
constexpr int STAGE_B    = 32768;              // A 16KB + B 16KB (fp16, k64)
constexpr int SMEM_BYTES = NSTAGE * STAGE_B;   // 96KB per CTA

// Scratch buffers (device globals: no allocation allowed)
__device__ __align__(256) __half g_ln [(size_t)M_TOK * C_DIM];
__device__ __align__(256) __half g_qkv[(size_t)M_TOK * 3 * C_DIM];
__device__ __align__(256) __half g_o  [(size_t)M_TOK * C_DIM];
__device__ __align__(256) float  g_h  [(size_t)M_TOK * C_DIM];
__device__ __align__(256) __half g_a1 [(size_t)M_TOK * MLP_HID];
// fp16 transposed weights [N][K]
__device__ __align__(256) __half g_bt_qkv [(size_t)3 * C_DIM * C_DIM];
__device__ __align__(256) __half g_bt_proj[(size_t)C_DIM * C_DIM];
__device__ __align__(256) __half g_bt_fc1 [(size_t)MLP_HID * C_DIM];
__device__ __align__(256) __half g_bt_fc2 [(size_t)C_DIM * MLP_HID];

// ---------------------------------------------------------------------------
// asm helpers (base-arch only: cp.async sm80, ldmatrix sm75, mma.sync sm80)
// ---------------------------------------------------------------------------
__device__ __forceinline__ uint32_t smem_u32(const void* p) {
    uint32_t a;
    asm("{ .reg .u64 t; cvta.to.shared.u64 t, %1; cvt.u32.u64 %0, t; }"
        : "=r"(a) : "l"(p));
    return a;
}
__device__ __forceinline__ void cp16(uint32_t dst, const void* src) {
    asm volatile("cp.async.cg.shared.global [%0], [%1], 16;"
                 :: "r"(dst), "l"(src) : "memory");
}
__device__ __forceinline__ void cp_commit() {
    asm volatile("cp.async.commit_group;" ::: "memory");
}
template <int N>
__device__ __forceinline__ void cp_wait() {
    asm volatile("cp.async.wait_group %0;" :: "n"(N) : "memory");
}
__device__ __forceinline__ void ldmx4(uint32_t& r0, uint32_t& r1,
                                      uint32_t& r2, uint32_t& r3, uint32_t addr) {
    asm volatile("ldmatrix.sync.aligned.m8n8.x4.shared.b16 {%0,%1,%2,%3}, [%4];"
                 : "=r"(r0), "=r"(r1), "=r"(r2), "=r"(r3) : "r"(addr));
}
__device__ __forceinline__ void mma16816(float* c, const uint32_t* a,
                                         const uint32_t* b) {
    asm volatile(
        "mma.sync.aligned.m16n8k16.row.col.f32.f16.f16.f32 "
        "{%0,%1,%2,%3}, {%4,%5,%6,%7}, {%8,%9}, {%0,%1,%2,%3};"
        : "+f"(c[0]), "+f"(c[1]), "+f"(c[2]), "+f"(c[3])
        : "r"(a[0]), "r"(a[1]), "r"(a[2]), "r"(a[3]), "r"(b[0]), "r"(b[1]));
}
// smem tile: [128 rows][64 fp16] = 128B rows (8x16B chunks), XOR-8 swizzle
__device__ __forceinline__ uint32_t sa_off(int row, int c4) {
    return (uint32_t)(row * 128 + ((c4 ^ (row & 7)) << 4));
}
__device__ __forceinline__ float gelu(float v) {
    return 0.5f * v * (1.0f + erff(v * 0.70710678118654752f));
}

// ---------------------------------------------------------------------------
// Weight prep: W[K][N] fp32 -> Wt[N][K] fp16, tiled transpose (coalesced
// on both sides). grid = (N/32, K/32), block = 256 (32x8).
// ---------------------------------------------------------------------------
__global__ __launch_bounds__(256) void prep_w(const float* __restrict__ W,
                                              __half* __restrict__ Wt,
                                              int K, int N) {
    __shared__ float t[32][33];
    int tx = threadIdx.x & 31, ty = threadIdx.x >> 5;
    int n0 = blockIdx.x * 32, k0 = blockIdx.y * 32;
    #pragma unroll
    for (int i = 0; i < 32; i += 8)
        t[ty + i][tx] = W[(size_t)(k0 + ty + i) * N + n0 + tx];
    __syncthreads();
    #pragma unroll
    for (int i = 0; i < 32; i += 8)
        Wt[(size_t)(n0 + ty + i) * K + k0 + tx] = __float2half_rn(t[tx][ty + i]);
}

// ---------------------------------------------------------------------------
// fp16 HMMA GEMM (f32 accumulate): C[M,N] = A[M,K] @ Bt[N,K]^T (+bias/res/gelu)
// 128x128 CTA tile, 128 thr, 4 warps (2x2 -> 64x64 warp tile),
// K-chunk 64, 3-stage cp.async pipeline, 2 CTAs/SM.
// EPI: 0 = +bias -> half ; 1 = +bias+res -> float ; 2 = gelu(+bias) -> half
// ---------------------------------------------------------------------------
template <int EPI>
__global__ __launch_bounds__(128, 2)
void gemm_hmma(const __half* __restrict__ A, const __half* __restrict__ Bt,
               const float* __restrict__ bias, const float* __restrict__ R,
               void* __restrict__ out, int M, int N, int K) {
    extern __shared__ __align__(128) char smem[];
    uint32_t sbase = smem_u32(smem);

    int tid = threadIdx.x, warp = tid >> 5, lane = tid & 31;
    int wm = warp >> 1, wn = warp & 1;
    int m0 = blockIdx.y * 128, n0 = blockIdx.x * 128;
    int NC = K >> 6;

    float acc[4][8][4];
    #pragma unroll
    for (int i = 0; i < 4; i++)
        #pragma unroll
        for (int j = 0; j < 8; j++)
            #pragma unroll
            for (int e = 0; e < 4; e++) acc[i][j][e] = 0.0f;

    auto load_chunk = [&](int kc, int s) {
        uint32_t ast = sbase + s * STAGE_B;
        uint32_t bst = ast + 16384;
        #pragma unroll
        for (int t = 0; t < 8; t++) {
            int seg = tid + t * 128;
            int row = seg >> 3, q = seg & 7;
            cp16(ast + sa_off(row, q),
                 A + (size_t)(m0 + row) * K + kc * 64 + q * 8);
            cp16(bst + sa_off(row, q),
                 Bt + (size_t)(n0 + row) * K + kc * 64 + q * 8);
        }
    };

    #pragma unroll
    for (int c = 0; c < NSTAGE - 1; c++) { load_chunk(c, c); cp_commit(); }

    int s_cur = 0, s_nxt = NSTAGE - 1;
    for (int c = 0; c < NC; c++) {
        cp_wait<NSTAGE - 2>();
        __syncthreads();
        int cn = c + NSTAGE - 1;
        if (cn < NC) load_chunk(cn, s_nxt);
        cp_commit();
        if (++s_nxt == NSTAGE) s_nxt = 0;

        uint32_t ast = sbase + s_cur * STAGE_B;
        uint32_t bst = ast + 16384;
        if (++s_cur == NSTAGE) s_cur = 0;

        #pragma unroll
        for (int kk = 0; kk < 4; kk++) {
            uint32_t a[4][4], b[4][4];
            #pragma unroll
            for (int i = 0; i < 4; i++) {
                int row = wm * 64 + i * 16 + (lane & 15);
                int c4  = kk * 2 + (lane >> 4);
                ldmx4(a[i][0], a[i][1], a[i][2], a[i][3], ast + sa_off(row, c4));
            }
            #pragma unroll
            for (int jp = 0; jp < 4; jp++) {
                int row = wn * 64 + jp * 16 + (lane & 7) + ((lane >> 4) << 3);
                int c4  = kk * 2 + ((lane >> 3) & 1);
                ldmx4(b[jp][0], b[jp][1], b[jp][2], b[jp][3], bst + sa_off(row, c4));
            }
            #pragma unroll
            for (int i = 0; i < 4; i++)
                #pragma unroll
                for (int jp = 0; jp < 4; jp++) {
                    mma16816(acc[i][jp * 2 + 0], a[i], &b[jp][0]);
                    mma16816(acc[i][jp * 2 + 1], a[i], &b[jp][2]);
                }
        }
    }

    // register epilogue
    int rbase = m0 + wm * 64 + (lane >> 2);
    #pragma unroll
    for (int i = 0; i < 4; i++) {
        #pragma unroll
        for (int j = 0; j < 8; j++) {
            int col = n0 + wn * 64 + j * 8 + ((lane & 3) << 1);
            float b0 = bias[col], b1 = bias[col + 1];
            #pragma unroll
            for (int hm = 0; hm < 2; hm++) {
                int row = rbase + i * 16 + hm * 8;
                float v0 = acc[i][j][hm * 2 + 0] + b0;
                float v1 = acc[i][j][hm * 2 + 1] + b1;
                if (EPI == 1) {
                    const float2 r2 = *reinterpret_cast<const float2*>(
                        R + (size_t)row * N + col);
                    v0 += r2.x; v1 += r2.y;
                    *reinterpret_cast<float2*>((float*)out + (size_t)row * N + col)
                        = make_float2(v0, v1);
                } else {
                    if (EPI == 2) { v0 = gelu(v0); v1 = gelu(v1); }
                    *reinterpret_cast<__half2*>((__half*)out + (size_t)row * N + col)
                        = __floats2half2_rn(v0, v1);
                }
            }
        }
    }
}

// ---------------------------------------------------------------------------
// LayerNorm: one warp per token, fp32 in -> fp16 out
// ---------------------------------------------------------------------------
__global__ __launch_bounds__(256) void ln_kernel(const float* __restrict__ x,
                                                 const float* __restrict__ g,
                                                 const float* __restrict__ b,
                                                 __half* __restrict__ y) {
    int warp = threadIdx.x >> 5, lane = threadIdx.x & 31;
    int m = blockIdx.x * 8 + warp;
    const float4* xr = reinterpret_cast<const float4*>(x + (size_t)m * C_DIM);
    float4 v0 = xr[lane], v1 = xr[lane + 32], v2 = xr[lane + 64];

    float s  = v0.x + v0.y + v0.z + v0.w + v1.x + v1.y + v1.z + v1.w
             + v2.x + v2.y + v2.z + v2.w;
    float sq = v0.x*v0.x + v0.y*v0.y + v0.z*v0.z + v0.w*v0.w
             + v1.x*v1.x + v1.y*v1.y + v1.z*v1.z + v1.w*v1.w
             + v2.x*v2.x + v2.y*v2.y + v2.z*v2.z + v2.w*v2.w;
    #pragma unroll
    for (int o = 16; o; o >>= 1) {
        s  += __shfl_xor_sync(0xffffffffu, s,  o);
        sq += __shfl_xor_sync(0xffffffffu, sq, o);
    }
    float mean = s * (1.0f / 384.0f);
    float var  = sq * (1.0f / 384.0f) - mean * mean;
    float rstd = rsqrtf(var + 1e-5f);

    const float4* gr = reinterpret_cast<const float4*>(g);
    const float4* br = reinterpret_cast<const float4*>(b);
    __half2* yr = reinterpret_cast<__half2*>(y + (size_t)m * C_DIM);
    #pragma unroll
    for (int t = 0; t < 3; t++) {
        int p = lane + 32 * t;
        float4 xv = (t == 0) ? v0 : (t == 1) ? v1 : v2;
        float4 gv = gr[p], bv = br[p];
        yr[p * 2 + 0] = __floats2half2_rn((xv.x - mean) * rstd * gv.x + bv.x,
                                          (xv.y - mean) * rstd * gv.y + bv.y);
        yr[p * 2 + 1] = __floats2half2_rn((xv.z - mean) * rstd * gv.z + bv.z,
                                          (xv.w - mean) * rstd * gv.w + bv.w);
    }
}

// ---------------------------------------------------------------------------
// Windowed shifted attention: one block per (head, window); fp16 I/O.
// Q,K kept as half2 in smem (80B row stride -> conflict-free LDS.128),
// QK dot via HFMA2 (4 independent half2 chains). V kept fp32 for PV.
// Rel-bias column preloaded to smem.
// ---------------------------------------------------------------------------
__global__ __launch_bounds__(256) void attn_kernel(const __half* __restrict__ qkv,
                                                   const float* __restrict__ table,
                                                   const int* __restrict__ relidx,
                                                   __half* __restrict__ o) {
    __shared__ __align__(16) __half2 q2[NWIN][40], k2[NWIN][40]; // 32 used, 80B stride
    __shared__ __align__(16) float vs[NWIN][36];
    __shared__ float ss[NWIN][52];
    __shared__ float sbias[(2 * WS - 1) * (2 * WS - 1)];         // 169
    __shared__ int   sidx[NWIN];

    int head = blockIdx.x;
    int w    = blockIdx.y;
    int tid  = threadIdx.x, warp = tid >> 5, lane = tid & 31;

    int b  = w >> 6;
    int wr = w & 63;
    int wi = wr >> 3, wj = wr & 7;

    if (tid < NWIN) {
        int i = tid / 7, j = tid - 7 * (tid / 7);
        int rr = wi * 7 + i + SHIFT; if (rr >= HDIM) rr -= HDIM;
        int cc = wj * 7 + j + SHIFT; if (cc >= HDIM) cc -= HDIM;
        sidx[tid] = b * (HDIM * HDIM) + rr * HDIM + cc;
    }
    if (tid < 169) sbias[tid] = table[tid * NHEADS + head];
    __syncthreads();

    // gather q,k (half2, 4 uint4 per row) and v (fp32)
    for (int idx = tid; idx < NWIN * 4; idx += 256) {
        int r = idx >> 2, c = idx & 3;
        const uint4* base = reinterpret_cast<const uint4*>(
            qkv + (size_t)sidx[r] * (3 * C_DIM) + head * HEADD);
        reinterpret_cast<uint4*>(&q2[r][0])[c] = base[c];
        reinterpret_cast<uint4*>(&k2[r][0])[c] = base[c + C_DIM / 8];
        uint4 vv = base[c + 2 * C_DIM / 8];
        const __half2* vh = reinterpret_cast<const __half2*>(&vv);
        float2 f0 = __half22float2(vh[0]), f1 = __half22float2(vh[1]);
        float2 f2 = __half22float2(vh[2]), f3 = __half22float2(vh[3]);
        float* vd = &vs[r][c * 8];
        vd[0] = f0.x; vd[1] = f0.y; vd[2] = f1.x; vd[3] = f1.y;
        vd[4] = f2.x; vd[5] = f2.y; vd[6] = f3.x; vd[7] = f3.y;
    }
    __syncthreads();

    const float scale = 0.17677669529663687f;
    for (int e = tid; e < NWIN * NWIN; e += 256) {
        int i = e / NWIN, j = e - i * NWIN;
        const uint4* qq = reinterpret_cast<const uint4*>(&q2[i][0]);
        const uint4* kk = reinterpret_cast<const uint4*>(&k2[j][0]);
        __half2 a0 = __float2half2_rn(0.f), a1 = a0, a2 = a0, a3 = a0;
        #pragma unroll
        for (int t = 0; t < 4; t++) {
            uint4 qa = qq[t], kb = kk[t];
            const __half2* qh = reinterpret_cast<const __half2*>(&qa);
            const __half2* kh = reinterpret_cast<const __half2*>(&kb);
            a0 = __hfma2(qh[0], kh[0], a0);
            a1 = __hfma2(qh[1], kh[1], a1);
            a2 = __hfma2(qh[2], kh[2], a2);
            a3 = __hfma2(qh[3], kh[3], a3);
        }
        float2 f0 = __half22float2(a0), f1 = __half22float2(a1);
        float2 f2 = __half22float2(a2), f3 = __half22float2(a3);
        float s = (f0.x + f0.y) + (f1.x + f1.y) + (f2.x + f2.y) + (f3.x + f3.y);
        ss[i][j] = s * scale + sbias[relidx[e]];
    }
    __syncthreads();

    for (int i = warp; i < NWIN; i += 8) {
        float mx = -1e30f;
        for (int j = lane; j < NWIN; j += 32) mx = fmaxf(mx, ss[i][j]);
        #pragma unroll
        for (int off = 16; off; off >>= 1)
            mx = fmaxf(mx, __shfl_xor_sync(0xffffffffu, mx, off));
        float sum = 0.0f;
        for (int j = lane; j < NWIN; j += 32) {
            float p = __expf(ss[i][j] - mx);
            ss[i][j] = p;
            sum += p;
        }
        #pragma unroll
        for (int off = 16; off; off >>= 1)
            sum += __shfl_xor_sync(0xffffffffu, sum, off);
        float inv = 1.0f / sum;
        for (int j = lane; j < NWIN; j += 32) ss[i][j] *= inv;
    }
    __syncthreads();

    // O = P @ V, float4 over head-dim (8 chunks of 4)
    for (int e = tid; e < NWIN * 8; e += 256) {
        int i = e >> 3, dq = e & 7;
        float ax = 0.f, ay = 0.f, az = 0.f, aw = 0.f;
        #pragma unroll 7
        for (int j = 0; j < NWIN; j++) {
            float p = ss[i][j];
            float4 v = *reinterpret_cast<const float4*>(&vs[j][dq * 4]);
            ax += p * v.x; ay += p * v.y; az += p * v.z; aw += p * v.w;
        }
        __half2 h0 = __floats2half2_rn(ax, ay);
        __half2 h1 = __floats2half2_rn(az, aw);
        uint2 pk = make_uint2(*reinterpret_cast<uint32_t*>(&h0),
                              *reinterpret_cast<uint32_t*>(&h1));
        *reinterpret_cast<uint2*>(o + (size_t)sidx[i] * C_DIM + head * HEADD + dq * 4)
            = pk;
    }
}

// ---------------------------------------------------------------------------
extern "C" void kernel_launch(void* const* d_in, const int* in_sizes, int n_in,
                              void* d_out, int out_size) {
    const float* x      = (const float*)d_in[0];
    const float* n1g    = (const float*)d_in[1];
    const float* n1b    = (const float*)d_in[2];
    const float* qkvw   = (const float*)d_in[3];
    const float* qkvb   = (const float*)d_in[4];
    const float* projw  = (const float*)d_in[5];
    const float* projb  = (const float*)d_in[6];
    const float* table  = (const float*)d_in[7];
    const float* n2g    = (const float*)d_in[8];
    const float* n2b    = (const float*)d_in[9];
    const float* fc1w   = (const float*)d_in[10];
    const float* fc1b   = (const float*)d_in[11];
    const float* fc2w   = (const float*)d_in[12];
    const float* fc2b   = (const float*)d_in[13];
    const int*   relidx = (const int*)d_in[14];
    float* out = (float*)d_out;

    __half *ln, *qkv, *o, *a1, *btq, *btp, *bt1, *bt2;
    float *h;
    cudaGetSymbolAddress((void**)&ln,  g_ln);
    cudaGetSymbolAddress((void**)&qkv, g_qkv);
    cudaGetSymbolAddress((void**)&o,   g_o);
    cudaGetSymbolAddress((void**)&h,   g_h);
    cudaGetSymbolAddress((void**)&a1,  g_a1);
    cudaGetSymbolAddress((void**)&btq, g_bt_qkv);
    cudaGetSymbolAddress((void**)&btp, g_bt_proj);
    cudaGetSymbolAddress((void**)&bt1, g_bt_fc1);
    cudaGetSymbolAddress((void**)&bt2, g_bt_fc2);

    cudaFuncSetAttribute(gemm_hmma<0>, cudaFuncAttributeMaxDynamicSharedMemorySize, SMEM_BYTES);
    cudaFuncSetAttribute(gemm_hmma<1>, cudaFuncAttributeMaxDynamicSharedMemorySize, SMEM_BYTES);
    cudaFuncSetAttribute(gemm_hmma<2>, cudaFuncAttributeMaxDynamicSharedMemorySize, SMEM_BYTES);

    // weight prep (fp32 [K][N] -> fp16 [N][K]) — tiled transpose, coalesced
    prep_w<<<dim3(3 * C_DIM / 32, C_DIM / 32), 256>>>(qkvw, btq, C_DIM, 3 * C_DIM);
    prep_w<<<dim3(C_DIM / 32, C_DIM / 32),     256>>>(projw, btp, C_DIM, C_DIM);
    prep_w<<<dim3(MLP_HID / 32, C_DIM / 32),   256>>>(fc1w, bt1, C_DIM, MLP_HID);
    prep_w<<<dim3(C_DIM / 32, MLP_HID / 32),   256>>>(fc2w, bt2, MLP_HID, C_DIM);

    // 1) LN1: x -> ln (fp16)
    ln_kernel<<<M_TOK / 8, 256>>>(x, n1g, n1b, ln);
    // 2) qkv = ln @ qkv_w + b   (fp16 out)
    gemm_hmma<0><<<dim3(3 * C_DIM / 128, M_TOK / 128), 128, SMEM_BYTES>>>(
        ln, btq, qkvb, nullptr, qkv, M_TOK, 3 * C_DIM, C_DIM);
    // 3) windowed attention (shift folded into indices), fp16 out
    attn_kernel<<<dim3(NHEADS, 2048), 256>>>(qkv, table, relidx, o);
    // 4) h = x + proj(o)   (fp32 out)
    gemm_hmma<1><<<dim3(C_DIM / 128, M_TOK / 128), 128, SMEM_BYTES>>>(
        o, btp, projb, x, h, M_TOK, C_DIM, C_DIM);
    // 5) LN2: h -> ln (fp16)
    ln_kernel<<<M_TOK / 8, 256>>>(h, n2g, n2b, ln);
    // 6) a1 = gelu(fc1(ln))  (fp16 out)
    gemm_hmma<2><<<dim3(MLP_HID / 128, M_TOK / 128), 128, SMEM_BYTES>>>(
        ln, bt1, fc1b, nullptr, a1, M_TOK, MLP_HID, C_DIM);
    // 7) out = h + fc2(a1)   (fp32 out)
    gemm_hmma<1><<<dim3(C_DIM / 128, M_TOK / 128), 128, SMEM_BYTES>>>(
        a1, bt2, fc2b, h, out, M_TOK, C_DIM, MLP_HID);
}